// round 2
// baseline (speedup 1.0000x reference)
#include <cuda_runtime.h>
#include <cstdint>

// ---------------- problem constants ----------------
// x: [16,3,256,256], ps=32 -> 1024 patches of 32x32 (d=1024), hidden=1536, c_f=64
#define NP   1024
#define DD   1024
#define HID  1536

// ---------------- scratch (device globals; no allocations) ----------------
__device__ float g_pr[NP * DD];        // grayscale patches [p][i*32+j]
__device__ float g_mag[NP * DD];       // gated FFT magnitude [p][j*32+k]
__device__ float g_hidden[NP * HID];   // relu(mag@W1+b1)
__device__ float g_wpart[NP * 16];     // per-row partial sums of mod (16 n-chunks)
__device__ float g_wf[NP];             // 1 + w_p
__device__ float g_psum[NP];           // sum(pr) per patch
__device__ float g_psumsq[NP];         // sum(pr^2) per patch
__device__ float g_stats[2];           // {mu, var} of x_rec

// ---------------- helpers ----------------
__device__ __forceinline__ float sigmoidf_(float x) { return 1.0f / (1.0f + __expf(-x)); }

__device__ __forceinline__ float tf32r(float f) {
    uint32_t u;
    asm("cvt.rna.tf32.f32 %0, %1;" : "=r"(u) : "f"(f));
    return __uint_as_float(u);
}

__device__ __forceinline__ void mma8(float* c, const uint32_t* a, const uint32_t* b) {
    asm volatile(
        "mma.sync.aligned.m16n8k8.row.col.f32.tf32.tf32.f32 "
        "{%0,%1,%2,%3}, {%4,%5,%6,%7}, {%8,%9}, {%0,%1,%2,%3};\n"
        : "+f"(c[0]), "+f"(c[1]), "+f"(c[2]), "+f"(c[3])
        : "r"(a[0]), "r"(a[1]), "r"(a[2]), "r"(a[3]), "r"(b[0]), "r"(b[1]));
}

// ====================================================================
// Kernel 1: grayscale + patchify + 32x32 DFT (two 1-D passes) + gate
//           also per-patch sum / sum-of-squares
// grid: 1024 blocks (one per patch), 256 threads
// ====================================================================
__global__ __launch_bounds__(256) void k_fft(const float* __restrict__ x,
                                             const float* __restrict__ lf,
                                             const float* __restrict__ mf,
                                             const float* __restrict__ hf) {
    __shared__ float sP[32][33];
    __shared__ float sYre[32][33];
    __shared__ float sYim[32][33];
    __shared__ float twc[32], tws[32];
    __shared__ float rA[8], rB[8];

    const int p = blockIdx.x;
    const int tid = threadIdx.x;
    const int b = p >> 6;
    const int gy = (p >> 3) & 7;
    const int gx = p & 7;

    if (tid < 32) {
        float ang = (float)tid * (1.0f / 16.0f);  // 2*pi*t/32 = pi*t/16
        twc[tid] = cospif(ang);
        tws[tid] = sinpif(ang);
    }

    // grayscale load + patch sums
    const float* xb = x + (size_t)b * 3 * 65536;
    float ls = 0.f, ls2 = 0.f;
#pragma unroll
    for (int ii = 0; ii < 4; ii++) {
        int idx = tid + ii * 256;
        int i = idx >> 5, j = idx & 31;
        int off = (gy * 32 + i) * 256 + gx * 32 + j;
        float v = 0.299f * xb[off] + 0.587f * xb[65536 + off] + 0.114f * xb[131072 + off];
        sP[i][j] = v;
        g_pr[p * DD + idx] = v;
        ls += v;
        ls2 += v * v;
    }
#pragma unroll
    for (int o = 16; o; o >>= 1) {
        ls += __shfl_xor_sync(0xffffffffu, ls, o);
        ls2 += __shfl_xor_sync(0xffffffffu, ls2, o);
    }
    if ((tid & 31) == 0) { rA[tid >> 5] = ls; rB[tid >> 5] = ls2; }
    __syncthreads();
    if (tid == 0) {
        float a = 0.f, c2 = 0.f;
#pragma unroll
        for (int q = 0; q < 8; q++) { a += rA[q]; c2 += rB[q]; }
        g_psum[p] = a;
        g_psumsq[p] = c2;
    }

    // stage 1: transform along columns index c  -> Y[r][k]
#pragma unroll
    for (int ii = 0; ii < 4; ii++) {
        int idx = tid + ii * 256;
        int r = idx >> 5, k = idx & 31;
        float sre = 0.f, sim = 0.f;
        int t = 0;
#pragma unroll
        for (int c = 0; c < 32; c++) {
            float v = sP[r][c];
            sre = fmaf(v, twc[t], sre);
            sim = fmaf(-v, tws[t], sim);
            t = (t + k) & 31;
        }
        sYre[r][k] = sre;
        sYim[r][k] = sim;
    }
    __syncthreads();

    const float sl = sigmoidf_(lf[0]);
    const float sm = sigmoidf_(mf[0]);
    const float sh = sigmoidf_(hf[0]);

    // stage 2: transform along rows index r -> F[j][k], magnitude + gate
#pragma unroll
    for (int ii = 0; ii < 4; ii++) {
        int idx = tid + ii * 256;
        int j = idx >> 5, k = idx & 31;
        float fre = 0.f, fim = 0.f;
        int t = 0;
#pragma unroll
        for (int r = 0; r < 32; r++) {
            float cc = twc[t], ss = tws[t];
            float yre = sYre[r][k], yim = sYim[r][k];
            fre = fmaf(yre, cc, fre);
            fre = fmaf(yim, ss, fre);
            fim = fmaf(yim, cc, fim);
            fim = fmaf(-yre, ss, fim);
            t = (t + j) & 31;
        }
        float mag = sqrtf(fre * fre + fim * fim) * 0.03125f;  // ortho norm (/32)
        float dy = (float)j - 15.5f, dx = (float)k - 15.5f;
        float r2 = dy * dy + dx * dx;
        // (rm/3)^2 = 480.5/9, (2rm/3)^2 = 4*480.5/9 ; r2 values are n+0.5 -> no ties
        float gate = (r2 <= 53.388889f) ? sl : ((r2 <= 213.555556f) ? sm : sh);
        g_mag[p * DD + idx] = mag * gate;
    }
}

// ====================================================================
// GEMM tiling: BM=128, BN=64, BK=32; 256 threads = 8 warps (4 m x 2 n),
// warp tile 32x32, mma m16n8k8 tf32.
// ====================================================================

// Kernel 2: hidden = relu(mag @ W1 + b1)    [1024 x 1536], K=1024
__global__ __launch_bounds__(256) void k_gemm1(const float* __restrict__ W1,
                                               const float* __restrict__ b1) {
    __shared__ float As[128][36];
    __shared__ float Bs[32][72];
    const int tid = threadIdx.x;
    const int m0 = blockIdx.x * 128, n0 = blockIdx.y * 64;
    const int warp = tid >> 5, lane = tid & 31;
    const int wm = warp & 3, wn = warp >> 2;
    const int g = lane >> 2, tg = lane & 3;

    float acc[2][4][4];
#pragma unroll
    for (int i = 0; i < 2; i++)
#pragma unroll
        for (int j = 0; j < 4; j++)
#pragma unroll
            for (int e = 0; e < 4; e++) acc[i][j][e] = 0.f;

    const int arow = tid >> 3, acol = (tid & 7) << 2;
    const int brow = tid >> 4, bcol = (tid & 15) << 2;

    for (int kt = 0; kt < 32; kt++) {
        const int k0 = kt * 32;
#pragma unroll
        for (int i = 0; i < 4; i++) {
            float4 v = *reinterpret_cast<const float4*>(&g_mag[(m0 + arow + i * 32) * 1024 + k0 + acol]);
            v.x = tf32r(v.x); v.y = tf32r(v.y); v.z = tf32r(v.z); v.w = tf32r(v.w);
            *reinterpret_cast<float4*>(&As[arow + i * 32][acol]) = v;
        }
#pragma unroll
        for (int i = 0; i < 2; i++) {
            float4 v = *reinterpret_cast<const float4*>(&W1[(k0 + brow + i * 16) * 1536 + n0 + bcol]);
            v.x = tf32r(v.x); v.y = tf32r(v.y); v.z = tf32r(v.z); v.w = tf32r(v.w);
            *reinterpret_cast<float4*>(&Bs[brow + i * 16][bcol]) = v;
        }
        __syncthreads();
#pragma unroll
        for (int ks = 0; ks < 4; ks++) {
            uint32_t afr[2][4], bfr[4][2];
#pragma unroll
            for (int mt = 0; mt < 2; mt++) {
                int mr = wm * 32 + mt * 16 + g;
                int kk = ks * 8 + tg;
                afr[mt][0] = __float_as_uint(As[mr][kk]);
                afr[mt][1] = __float_as_uint(As[mr + 8][kk]);
                afr[mt][2] = __float_as_uint(As[mr][kk + 4]);
                afr[mt][3] = __float_as_uint(As[mr + 8][kk + 4]);
            }
#pragma unroll
            for (int nt = 0; nt < 4; nt++) {
                int nc = wn * 32 + nt * 8 + g;
                bfr[nt][0] = __float_as_uint(Bs[ks * 8 + tg][nc]);
                bfr[nt][1] = __float_as_uint(Bs[ks * 8 + tg + 4][nc]);
            }
#pragma unroll
            for (int mt = 0; mt < 2; mt++)
#pragma unroll
                for (int nt = 0; nt < 4; nt++) mma8(acc[mt][nt], afr[mt], bfr[nt]);
        }
        __syncthreads();
    }

#pragma unroll
    for (int mt = 0; mt < 2; mt++) {
        int row0 = m0 + wm * 32 + mt * 16 + g;
#pragma unroll
        for (int nt = 0; nt < 4; nt++) {
            int col = n0 + wn * 32 + nt * 8 + tg * 2;
            float bb0 = b1[col], bb1 = b1[col + 1];
            float2 o;
            o.x = fmaxf(acc[mt][nt][0] + bb0, 0.f);
            o.y = fmaxf(acc[mt][nt][1] + bb1, 0.f);
            *reinterpret_cast<float2*>(&g_hidden[row0 * 1536 + col]) = o;
            o.x = fmaxf(acc[mt][nt][2] + bb0, 0.f);
            o.y = fmaxf(acc[mt][nt][3] + bb1, 0.f);
            *reinterpret_cast<float2*>(&g_hidden[(row0 + 8) * 1536 + col]) = o;
        }
    }
}

// Kernel 3: attn = sigmoid(hidden @ W2 + b2); rowsum of (mag*attn) -> g_wpart
// K=1536, N=1024. grid (8, 16). Deterministic (no atomics).
__global__ __launch_bounds__(256) void k_gemm2(const float* __restrict__ W2,
                                               const float* __restrict__ b2) {
    __shared__ float As[128][36];
    __shared__ float Bs[32][72];
    __shared__ float sRow[128][2];
    const int tid = threadIdx.x;
    const int m0 = blockIdx.x * 128, n0 = blockIdx.y * 64;
    const int warp = tid >> 5, lane = tid & 31;
    const int wm = warp & 3, wn = warp >> 2;
    const int g = lane >> 2, tg = lane & 3;

    float acc[2][4][4];
#pragma unroll
    for (int i = 0; i < 2; i++)
#pragma unroll
        for (int j = 0; j < 4; j++)
#pragma unroll
            for (int e = 0; e < 4; e++) acc[i][j][e] = 0.f;

    const int arow = tid >> 3, acol = (tid & 7) << 2;
    const int brow = tid >> 4, bcol = (tid & 15) << 2;

    for (int kt = 0; kt < 48; kt++) {
        const int k0 = kt * 32;
#pragma unroll
        for (int i = 0; i < 4; i++) {
            float4 v = *reinterpret_cast<const float4*>(&g_hidden[(m0 + arow + i * 32) * 1536 + k0 + acol]);
            v.x = tf32r(v.x); v.y = tf32r(v.y); v.z = tf32r(v.z); v.w = tf32r(v.w);
            *reinterpret_cast<float4*>(&As[arow + i * 32][acol]) = v;
        }
#pragma unroll
        for (int i = 0; i < 2; i++) {
            float4 v = *reinterpret_cast<const float4*>(&W2[(k0 + brow + i * 16) * 1024 + n0 + bcol]);
            v.x = tf32r(v.x); v.y = tf32r(v.y); v.z = tf32r(v.z); v.w = tf32r(v.w);
            *reinterpret_cast<float4*>(&Bs[brow + i * 16][bcol]) = v;
        }
        __syncthreads();
#pragma unroll
        for (int ks = 0; ks < 4; ks++) {
            uint32_t afr[2][4], bfr[4][2];
#pragma unroll
            for (int mt = 0; mt < 2; mt++) {
                int mr = wm * 32 + mt * 16 + g;
                int kk = ks * 8 + tg;
                afr[mt][0] = __float_as_uint(As[mr][kk]);
                afr[mt][1] = __float_as_uint(As[mr + 8][kk]);
                afr[mt][2] = __float_as_uint(As[mr][kk + 4]);
                afr[mt][3] = __float_as_uint(As[mr + 8][kk + 4]);
            }
#pragma unroll
            for (int nt = 0; nt < 4; nt++) {
                int nc = wn * 32 + nt * 8 + g;
                bfr[nt][0] = __float_as_uint(Bs[ks * 8 + tg][nc]);
                bfr[nt][1] = __float_as_uint(Bs[ks * 8 + tg + 4][nc]);
            }
#pragma unroll
            for (int mt = 0; mt < 2; mt++)
#pragma unroll
                for (int nt = 0; nt < 4; nt++) mma8(acc[mt][nt], afr[mt], bfr[nt]);
        }
        __syncthreads();
    }

    // epilogue: sigmoid, multiply by mag, per-row partial sums
    float rs[2][2] = {{0.f, 0.f}, {0.f, 0.f}};
#pragma unroll
    for (int mt = 0; mt < 2; mt++) {
        int row0 = m0 + wm * 32 + mt * 16 + g;
#pragma unroll
        for (int nt = 0; nt < 4; nt++) {
            int col = n0 + wn * 32 + nt * 8 + tg * 2;
            float bb0 = b2[col], bb1 = b2[col + 1];
            rs[mt][0] += g_mag[row0 * 1024 + col]       * sigmoidf_(acc[mt][nt][0] + bb0);
            rs[mt][0] += g_mag[row0 * 1024 + col + 1]   * sigmoidf_(acc[mt][nt][1] + bb1);
            rs[mt][1] += g_mag[(row0 + 8) * 1024 + col]     * sigmoidf_(acc[mt][nt][2] + bb0);
            rs[mt][1] += g_mag[(row0 + 8) * 1024 + col + 1] * sigmoidf_(acc[mt][nt][3] + bb1);
        }
    }
#pragma unroll
    for (int mt = 0; mt < 2; mt++)
#pragma unroll
        for (int hh = 0; hh < 2; hh++) {
            float v = rs[mt][hh];
            v += __shfl_xor_sync(0xffffffffu, v, 1);
            v += __shfl_xor_sync(0xffffffffu, v, 2);
            if (tg == 0) sRow[wm * 32 + mt * 16 + hh * 8 + g][wn] = v;
        }
    __syncthreads();
    if (tid < 128) g_wpart[(m0 + tid) * 16 + blockIdx.y] = sRow[tid][0] + sRow[tid][1];
}

// ====================================================================
// Kernel 4: per-patch w, global mean/var of x_rec (tiny). 1 block, 1024 thr.
// ====================================================================
__global__ __launch_bounds__(1024) void k_stats() {
    __shared__ float sA[1024], sB[1024];
    const int t = threadIdx.x;
    float s = 0.f;
#pragma unroll
    for (int j = 0; j < 16; j++) s += g_wpart[t * 16 + j];
    float wf = 1.0f + s * (1.0f / 1024.0f);
    g_wf[t] = wf;
    sA[t] = wf * g_psum[t];
    sB[t] = wf * wf * g_psumsq[t];
    __syncthreads();
    for (int o = 512; o; o >>= 1) {
        if (t < o) { sA[t] += sA[t + o]; sB[t] += sB[t + o]; }
        __syncthreads();
    }
    if (t == 0) {
        float mu = sA[0] * (1.0f / 1048576.0f);
        float ex2 = sB[0] * (1.0f / 1048576.0f);
        g_stats[0] = mu;
        g_stats[1] = ex2 - mu * mu;
    }
}

// ====================================================================
// Kernel 5: out[b,c,h,w] = relu(s_c*(x_rec - mu) + beta_c)  — write-bound
// grid 1024 blocks x 256 threads; each thread: one float4 spatial, 64 channels
// ====================================================================
__global__ __launch_bounds__(256) void k_final(const float* __restrict__ wproj,
                                               const float* __restrict__ gamma,
                                               const float* __restrict__ beta,
                                               float* __restrict__ out) {
    __shared__ float sS[64], sO[64];
    const int tid = threadIdx.x;
    if (tid < 64) {
        float mu = g_stats[0], var = g_stats[1];
        float wp = wproj[tid];
        float sc = gamma[tid] * wp * rsqrtf(fmaf(wp * wp, var, 1e-5f));
        sS[tid] = sc;
        sO[tid] = beta[tid] - sc * mu;
    }
    __syncthreads();

    const int t = blockIdx.x * 256 + tid;
    const int b = t >> 14;
    const int rem = t & 16383;
    const int h = rem >> 6;
    const int w4 = rem & 63;
    const int p = b * 64 + (h >> 5) * 8 + (w4 >> 3);

    float4 xr = *reinterpret_cast<const float4*>(&g_pr[p * DD + (h & 31) * 32 + (w4 & 7) * 4]);
    const float wf = g_wf[p];
    xr.x *= wf; xr.y *= wf; xr.z *= wf; xr.w *= wf;

    float* ob = out + ((size_t)b << 22) + (h << 8) + (w4 << 2);
#pragma unroll 8
    for (int ch = 0; ch < 64; ch++) {
        float s = sS[ch], o = sO[ch];
        float4 v;
        v.x = fmaxf(fmaf(s, xr.x, o), 0.f);
        v.y = fmaxf(fmaf(s, xr.y, o), 0.f);
        v.z = fmaxf(fmaf(s, xr.z, o), 0.f);
        v.w = fmaxf(fmaf(s, xr.w, o), 0.f);
        *reinterpret_cast<float4*>(ob + ((size_t)ch << 16)) = v;
    }
}

// ====================================================================
extern "C" void kernel_launch(void* const* d_in, const int* in_sizes, int n_in,
                              void* d_out, int out_size) {
    (void)in_sizes; (void)n_in; (void)out_size;
    const float* x     = (const float*)d_in[0];
    const float* W1    = (const float*)d_in[1];
    const float* b1    = (const float*)d_in[2];
    const float* W2    = (const float*)d_in[3];
    const float* b2    = (const float*)d_in[4];
    const float* wproj = (const float*)d_in[5];
    const float* gamma = (const float*)d_in[6];
    const float* beta  = (const float*)d_in[7];
    const float* lf    = (const float*)d_in[8];
    const float* mf    = (const float*)d_in[9];
    const float* hf    = (const float*)d_in[10];
    float* out = (float*)d_out;

    k_fft<<<1024, 256>>>(x, lf, mf, hf);
    k_gemm1<<<dim3(8, 24), 256>>>(W1, b1);
    k_gemm2<<<dim3(8, 16), 256>>>(W2, b2);
    k_stats<<<1, 1024>>>();
    k_final<<<1024, 256>>>(wproj, gamma, beta, out);
}

// round 5
// speedup vs baseline: 1.3181x; 1.3181x over previous
#include <cuda_runtime.h>
#include <cstdint>

// ---------------- problem constants ----------------
#define NP   1024
#define DD   1024
#define HID  1536

// ---------------- scratch (device globals; no allocations) ----------------
__device__ float g_pr[NP * DD];
__device__ float g_mag[NP * DD];
__device__ float g_hidden[NP * HID];
__device__ float g_wpart[NP * 16];
__device__ float g_wf[NP];
__device__ float g_psum[NP];
__device__ float g_psumsq[NP];
__device__ float g_stats[2];

// ---------------- helpers ----------------
__device__ __forceinline__ float sigmoidf_(float x) { return 1.0f / (1.0f + __expf(-x)); }

__device__ __forceinline__ void mma8(float* c, const uint32_t* a, const uint32_t* b) {
    asm volatile(
        "mma.sync.aligned.m16n8k8.row.col.f32.tf32.tf32.f32 "
        "{%0,%1,%2,%3}, {%4,%5,%6,%7}, {%8,%9}, {%0,%1,%2,%3};\n"
        : "+f"(c[0]), "+f"(c[1]), "+f"(c[2]), "+f"(c[3])
        : "r"(a[0]), "r"(a[1]), "r"(a[2]), "r"(a[3]), "r"(b[0]), "r"(b[1]));
}

__device__ __forceinline__ void cpa16(uint32_t s, const void* g) {
    asm volatile("cp.async.cg.shared.global [%0], [%1], 16;\n" :: "r"(s), "l"(g));
}
__device__ __forceinline__ void cpa_commit() { asm volatile("cp.async.commit_group;\n"); }
__device__ __forceinline__ void cpa_wait1() { asm volatile("cp.async.wait_group 1;\n"); }
__device__ __forceinline__ void cpa_wait0() { asm volatile("cp.async.wait_group 0;\n"); }

// swizzled float-offsets inside one tile buffer
// A tile: 128 rows x 32 cols. chunk (4 floats) swizzle: c' = (c + (r&7)) & 7
__device__ __forceinline__ int a_off(int r, int c) {
    return r * 32 + ((((c >> 2) + (r & 7)) & 7) << 2) + (c & 3);
}
// B tile: 32 rows x 64 cols. chunk swizzle: c' = (c + 2*(r&3)) & 15
__device__ __forceinline__ int b_off(int r, int c) {
    return r * 64 + ((((c >> 2) + 2 * (r & 3)) & 15) << 2) + (c & 3);
}

#define A_BUF 4096            // 128*32 floats
#define B_BUF 2048            // 32*64 floats
#define GSMEM_BYTES ((2 * A_BUF + 2 * B_BUF) * 4)   // 49152 = 48 KB (default cap, no opt-in)

// ====================================================================
// Kernel 1: grayscale + patchify + 32x32 DFT + gate + patch sums
// ====================================================================
__global__ __launch_bounds__(256) void k_fft(const float* __restrict__ x,
                                             const float* __restrict__ lf,
                                             const float* __restrict__ mf,
                                             const float* __restrict__ hf) {
    __shared__ float sP[32][33];
    __shared__ float sYre[32][33];
    __shared__ float sYim[32][33];
    __shared__ float twc[32], tws[32];
    __shared__ float rA[8], rB[8];

    const int p = blockIdx.x;
    const int tid = threadIdx.x;
    const int b = p >> 6;
    const int gy = (p >> 3) & 7;
    const int gx = p & 7;

    if (tid < 32) {
        float ang = (float)tid * (1.0f / 16.0f);
        twc[tid] = cospif(ang);
        tws[tid] = sinpif(ang);
    }

    const float* xb = x + (size_t)b * 3 * 65536;
    float ls = 0.f, ls2 = 0.f;
#pragma unroll
    for (int ii = 0; ii < 4; ii++) {
        int idx = tid + ii * 256;
        int i = idx >> 5, j = idx & 31;
        int off = (gy * 32 + i) * 256 + gx * 32 + j;
        float v = 0.299f * xb[off] + 0.587f * xb[65536 + off] + 0.114f * xb[131072 + off];
        sP[i][j] = v;
        g_pr[p * DD + idx] = v;
        ls += v;
        ls2 += v * v;
    }
#pragma unroll
    for (int o = 16; o; o >>= 1) {
        ls += __shfl_xor_sync(0xffffffffu, ls, o);
        ls2 += __shfl_xor_sync(0xffffffffu, ls2, o);
    }
    if ((tid & 31) == 0) { rA[tid >> 5] = ls; rB[tid >> 5] = ls2; }
    __syncthreads();
    if (tid == 0) {
        float a = 0.f, c2 = 0.f;
#pragma unroll
        for (int q = 0; q < 8; q++) { a += rA[q]; c2 += rB[q]; }
        g_psum[p] = a;
        g_psumsq[p] = c2;
    }

#pragma unroll
    for (int ii = 0; ii < 4; ii++) {
        int idx = tid + ii * 256;
        int r = idx >> 5, k = idx & 31;
        float sre = 0.f, sim = 0.f;
        int t = 0;
#pragma unroll
        for (int c = 0; c < 32; c++) {
            float v = sP[r][c];
            sre = fmaf(v, twc[t], sre);
            sim = fmaf(-v, tws[t], sim);
            t = (t + k) & 31;
        }
        sYre[r][k] = sre;
        sYim[r][k] = sim;
    }
    __syncthreads();

    const float sl = sigmoidf_(lf[0]);
    const float sm = sigmoidf_(mf[0]);
    const float sh = sigmoidf_(hf[0]);

#pragma unroll
    for (int ii = 0; ii < 4; ii++) {
        int idx = tid + ii * 256;
        int j = idx >> 5, k = idx & 31;
        float fre = 0.f, fim = 0.f;
        int t = 0;
#pragma unroll
        for (int r = 0; r < 32; r++) {
            float cc = twc[t], ss = tws[t];
            float yre = sYre[r][k], yim = sYim[r][k];
            fre = fmaf(yre, cc, fre);
            fre = fmaf(yim, ss, fre);
            fim = fmaf(yim, cc, fim);
            fim = fmaf(-yre, ss, fim);
            t = (t + j) & 31;
        }
        float mag = sqrtf(fre * fre + fim * fim) * 0.03125f;
        float dy = (float)j - 15.5f, dx = (float)k - 15.5f;
        float r2 = dy * dy + dx * dx;
        float gate = (r2 <= 53.388889f) ? sl : ((r2 <= 213.555556f) ? sm : sh);
        g_mag[p * DD + idx] = mag * gate;
    }
}

// ====================================================================
// GEMM: BM=128, BN=64, BK=32; 256 threads = 8 warps (4m x 2n),
// double-buffered smem (swizzled, 48 KB total) via cp.async.
// ====================================================================

// Kernel 2: hidden = relu(mag @ W1 + b1)   M=1024 N=1536 K=1024
__global__ __launch_bounds__(256) void k_gemm1(const float* __restrict__ W1,
                                               const float* __restrict__ b1) {
    extern __shared__ float smem[];
    float* As = smem;                 // [2][A_BUF]
    float* Bs = smem + 2 * A_BUF;     // [2][B_BUF]

    const int tid = threadIdx.x;
    const int m0 = blockIdx.x * 128, n0 = blockIdx.y * 64;
    const int warp = tid >> 5, lane = tid & 31;
    const int wm = warp & 3, wn = warp >> 2;
    const int g = lane >> 2, tg = lane & 3;

    float acc[2][4][4];
#pragma unroll
    for (int i = 0; i < 2; i++)
#pragma unroll
        for (int j = 0; j < 4; j++)
#pragma unroll
            for (int e = 0; e < 4; e++) acc[i][j][e] = 0.f;

    const int arow = tid >> 3, acol = (tid & 7) << 2;     // A: 32 rows/pass x 8 chunks
    const int brow = tid >> 4, bcol = (tid & 15) << 2;    // B: 16 rows/pass x 16 chunks
    const uint32_t sA0 = (uint32_t)__cvta_generic_to_shared(As);
    const uint32_t sB0 = (uint32_t)__cvta_generic_to_shared(Bs);

    // issue tile 0
    {
#pragma unroll
        for (int i = 0; i < 4; i++)
            cpa16(sA0 + a_off(arow + i * 32, acol) * 4,
                  &g_mag[(m0 + arow + i * 32) * 1024 + acol]);
#pragma unroll
        for (int i = 0; i < 2; i++)
            cpa16(sB0 + b_off(brow + i * 16, bcol) * 4,
                  &W1[(brow + i * 16) * 1536 + n0 + bcol]);
        cpa_commit();
    }

    for (int kt = 0; kt < 32; kt++) {
        const int cur = kt & 1;
        if (kt < 31) {
            const int k0 = (kt + 1) * 32;
            const int nb = cur ^ 1;
#pragma unroll
            for (int i = 0; i < 4; i++)
                cpa16(sA0 + (nb * A_BUF + a_off(arow + i * 32, acol)) * 4,
                      &g_mag[(m0 + arow + i * 32) * 1024 + k0 + acol]);
#pragma unroll
            for (int i = 0; i < 2; i++)
                cpa16(sB0 + (nb * B_BUF + b_off(brow + i * 16, bcol)) * 4,
                      &W1[(k0 + brow + i * 16) * 1536 + n0 + bcol]);
            cpa_commit();
            cpa_wait1();
        } else {
            cpa_wait0();
        }
        __syncthreads();

        const float* Ac = As + cur * A_BUF;
        const float* Bc = Bs + cur * B_BUF;
#pragma unroll
        for (int ks = 0; ks < 4; ks++) {
            uint32_t afr[2][4], bfr[4][2];
#pragma unroll
            for (int mt = 0; mt < 2; mt++) {
                int mr = wm * 32 + mt * 16 + g;
                int kk = ks * 8 + tg;
                afr[mt][0] = __float_as_uint(Ac[a_off(mr, kk)]);
                afr[mt][1] = __float_as_uint(Ac[a_off(mr + 8, kk)]);
                afr[mt][2] = __float_as_uint(Ac[a_off(mr, kk + 4)]);
                afr[mt][3] = __float_as_uint(Ac[a_off(mr + 8, kk + 4)]);
            }
#pragma unroll
            for (int nt = 0; nt < 4; nt++) {
                int nc = wn * 32 + nt * 8 + g;
                bfr[nt][0] = __float_as_uint(Bc[b_off(ks * 8 + tg, nc)]);
                bfr[nt][1] = __float_as_uint(Bc[b_off(ks * 8 + tg + 4, nc)]);
            }
#pragma unroll
            for (int mt = 0; mt < 2; mt++)
#pragma unroll
                for (int nt = 0; nt < 4; nt++) mma8(acc[mt][nt], afr[mt], bfr[nt]);
        }
        __syncthreads();
    }

#pragma unroll
    for (int mt = 0; mt < 2; mt++) {
        int row0 = m0 + wm * 32 + mt * 16 + g;
#pragma unroll
        for (int nt = 0; nt < 4; nt++) {
            int col = n0 + wn * 32 + nt * 8 + tg * 2;
            float bb0 = b1[col], bb1 = b1[col + 1];
            float2 o;
            o.x = fmaxf(acc[mt][nt][0] + bb0, 0.f);
            o.y = fmaxf(acc[mt][nt][1] + bb1, 0.f);
            *reinterpret_cast<float2*>(&g_hidden[row0 * 1536 + col]) = o;
            o.x = fmaxf(acc[mt][nt][2] + bb0, 0.f);
            o.y = fmaxf(acc[mt][nt][3] + bb1, 0.f);
            *reinterpret_cast<float2*>(&g_hidden[(row0 + 8) * 1536 + col]) = o;
        }
    }
}

// Kernel 3: attn = sigmoid(hidden @ W2 + b2); rowsum(mag*attn) -> g_wpart
__global__ __launch_bounds__(256) void k_gemm2(const float* __restrict__ W2,
                                               const float* __restrict__ b2) {
    extern __shared__ float smem[];
    float* As = smem;
    float* Bs = smem + 2 * A_BUF;
    float (*sRow)[2] = reinterpret_cast<float(*)[2]>(smem);  // reused after mainloop

    const int tid = threadIdx.x;
    const int m0 = blockIdx.x * 128, n0 = blockIdx.y * 64;
    const int warp = tid >> 5, lane = tid & 31;
    const int wm = warp & 3, wn = warp >> 2;
    const int g = lane >> 2, tg = lane & 3;

    float acc[2][4][4];
#pragma unroll
    for (int i = 0; i < 2; i++)
#pragma unroll
        for (int j = 0; j < 4; j++)
#pragma unroll
            for (int e = 0; e < 4; e++) acc[i][j][e] = 0.f;

    const int arow = tid >> 3, acol = (tid & 7) << 2;
    const int brow = tid >> 4, bcol = (tid & 15) << 2;
    const uint32_t sA0 = (uint32_t)__cvta_generic_to_shared(As);
    const uint32_t sB0 = (uint32_t)__cvta_generic_to_shared(Bs);

    {
#pragma unroll
        for (int i = 0; i < 4; i++)
            cpa16(sA0 + a_off(arow + i * 32, acol) * 4,
                  &g_hidden[(m0 + arow + i * 32) * 1536 + acol]);
#pragma unroll
        for (int i = 0; i < 2; i++)
            cpa16(sB0 + b_off(brow + i * 16, bcol) * 4,
                  &W2[(brow + i * 16) * 1024 + n0 + bcol]);
        cpa_commit();
    }

    for (int kt = 0; kt < 48; kt++) {
        const int cur = kt & 1;
        if (kt < 47) {
            const int k0 = (kt + 1) * 32;
            const int nb = cur ^ 1;
#pragma unroll
            for (int i = 0; i < 4; i++)
                cpa16(sA0 + (nb * A_BUF + a_off(arow + i * 32, acol)) * 4,
                      &g_hidden[(m0 + arow + i * 32) * 1536 + k0 + acol]);
#pragma unroll
            for (int i = 0; i < 2; i++)
                cpa16(sB0 + (nb * B_BUF + b_off(brow + i * 16, bcol)) * 4,
                      &W2[(k0 + brow + i * 16) * 1024 + n0 + bcol]);
            cpa_commit();
            cpa_wait1();
        } else {
            cpa_wait0();
        }
        __syncthreads();

        const float* Ac = As + cur * A_BUF;
        const float* Bc = Bs + cur * B_BUF;
#pragma unroll
        for (int ks = 0; ks < 4; ks++) {
            uint32_t afr[2][4], bfr[4][2];
#pragma unroll
            for (int mt = 0; mt < 2; mt++) {
                int mr = wm * 32 + mt * 16 + g;
                int kk = ks * 8 + tg;
                afr[mt][0] = __float_as_uint(Ac[a_off(mr, kk)]);
                afr[mt][1] = __float_as_uint(Ac[a_off(mr + 8, kk)]);
                afr[mt][2] = __float_as_uint(Ac[a_off(mr, kk + 4)]);
                afr[mt][3] = __float_as_uint(Ac[a_off(mr + 8, kk + 4)]);
            }
#pragma unroll
            for (int nt = 0; nt < 4; nt++) {
                int nc = wn * 32 + nt * 8 + g;
                bfr[nt][0] = __float_as_uint(Bc[b_off(ks * 8 + tg, nc)]);
                bfr[nt][1] = __float_as_uint(Bc[b_off(ks * 8 + tg + 4, nc)]);
            }
#pragma unroll
            for (int mt = 0; mt < 2; mt++)
#pragma unroll
                for (int nt = 0; nt < 4; nt++) mma8(acc[mt][nt], afr[mt], bfr[nt]);
        }
        __syncthreads();
    }

    float rs[2][2] = {{0.f, 0.f}, {0.f, 0.f}};
#pragma unroll
    for (int mt = 0; mt < 2; mt++) {
        int row0 = m0 + wm * 32 + mt * 16 + g;
#pragma unroll
        for (int nt = 0; nt < 4; nt++) {
            int col = n0 + wn * 32 + nt * 8 + tg * 2;
            float bb0 = b2[col], bb1 = b2[col + 1];
            rs[mt][0] += g_mag[row0 * 1024 + col]           * sigmoidf_(acc[mt][nt][0] + bb0);
            rs[mt][0] += g_mag[row0 * 1024 + col + 1]       * sigmoidf_(acc[mt][nt][1] + bb1);
            rs[mt][1] += g_mag[(row0 + 8) * 1024 + col]     * sigmoidf_(acc[mt][nt][2] + bb0);
            rs[mt][1] += g_mag[(row0 + 8) * 1024 + col + 1] * sigmoidf_(acc[mt][nt][3] + bb1);
        }
    }
#pragma unroll
    for (int mt = 0; mt < 2; mt++)
#pragma unroll
        for (int hh = 0; hh < 2; hh++) {
            float v = rs[mt][hh];
            v += __shfl_xor_sync(0xffffffffu, v, 1);
            v += __shfl_xor_sync(0xffffffffu, v, 2);
            if (tg == 0) sRow[wm * 32 + mt * 16 + hh * 8 + g][wn] = v;
        }
    __syncthreads();
    if (tid < 128) g_wpart[(m0 + tid) * 16 + blockIdx.y] = sRow[tid][0] + sRow[tid][1];
}

// ====================================================================
// Kernel 4: per-patch w + global stats (warp-shuffle version)
// ====================================================================
__global__ __launch_bounds__(1024) void k_stats() {
    __shared__ float sA[32], sB[32];
    const int t = threadIdx.x;
    const float4* wp4 = reinterpret_cast<const float4*>(g_wpart) + t * 4;
    float4 a = wp4[0], b4 = wp4[1], c4 = wp4[2], d4 = wp4[3];
    float s = (a.x + a.y + a.z + a.w) + (b4.x + b4.y + b4.z + b4.w)
            + (c4.x + c4.y + c4.z + c4.w) + (d4.x + d4.y + d4.z + d4.w);
    float wf = 1.0f + s * (1.0f / 1024.0f);
    g_wf[t] = wf;
    float va = wf * g_psum[t];
    float vb = wf * wf * g_psumsq[t];
#pragma unroll
    for (int o = 16; o; o >>= 1) {
        va += __shfl_xor_sync(0xffffffffu, va, o);
        vb += __shfl_xor_sync(0xffffffffu, vb, o);
    }
    if ((t & 31) == 0) { sA[t >> 5] = va; sB[t >> 5] = vb; }
    __syncthreads();
    if (t < 32) {
        float xa = sA[t], xb = sB[t];
#pragma unroll
        for (int o = 16; o; o >>= 1) {
            xa += __shfl_xor_sync(0xffffffffu, xa, o);
            xb += __shfl_xor_sync(0xffffffffu, xb, o);
        }
        if (t == 0) {
            float mu = xa * (1.0f / 1048576.0f);
            float ex2 = xb * (1.0f / 1048576.0f);
            g_stats[0] = mu;
            g_stats[1] = ex2 - mu * mu;
        }
    }
}

// ====================================================================
// Kernel 5: out = relu(s_c*(x_rec) + o_c) — write-bound
// ====================================================================
__global__ __launch_bounds__(256) void k_final(const float* __restrict__ wproj,
                                               const float* __restrict__ gamma,
                                               const float* __restrict__ beta,
                                               float* __restrict__ out) {
    __shared__ float sS[64], sO[64];
    const int tid = threadIdx.x;
    if (tid < 64) {
        float mu = g_stats[0], var = g_stats[1];
        float wp = wproj[tid];
        float sc = gamma[tid] * wp * rsqrtf(fmaf(wp * wp, var, 1e-5f));
        sS[tid] = sc;
        sO[tid] = beta[tid] - sc * mu;
    }
    __syncthreads();

    const int t = blockIdx.x * 256 + tid;
    const int b = t >> 14;
    const int rem = t & 16383;
    const int h = rem >> 6;
    const int w4 = rem & 63;
    const int p = b * 64 + (h >> 5) * 8 + (w4 >> 3);

    float4 xr = *reinterpret_cast<const float4*>(&g_pr[p * DD + (h & 31) * 32 + (w4 & 7) * 4]);
    const float wf = g_wf[p];
    xr.x *= wf; xr.y *= wf; xr.z *= wf; xr.w *= wf;

    float* ob = out + ((size_t)b << 22) + (h << 8) + (w4 << 2);
#pragma unroll 8
    for (int ch = 0; ch < 64; ch++) {
        float s = sS[ch], o = sO[ch];
        float4 v;
        v.x = fmaxf(fmaf(s, xr.x, o), 0.f);
        v.y = fmaxf(fmaf(s, xr.y, o), 0.f);
        v.z = fmaxf(fmaf(s, xr.z, o), 0.f);
        v.w = fmaxf(fmaf(s, xr.w, o), 0.f);
        *reinterpret_cast<float4*>(ob + ((size_t)ch << 16)) = v;
    }
}

// ====================================================================
extern "C" void kernel_launch(void* const* d_in, const int* in_sizes, int n_in,
                              void* d_out, int out_size) {
    (void)in_sizes; (void)n_in; (void)out_size;
    const float* x     = (const float*)d_in[0];
    const float* W1    = (const float*)d_in[1];
    const float* b1    = (const float*)d_in[2];
    const float* W2    = (const float*)d_in[3];
    const float* b2    = (const float*)d_in[4];
    const float* wproj = (const float*)d_in[5];
    const float* gamma = (const float*)d_in[6];
    const float* beta  = (const float*)d_in[7];
    const float* lf    = (const float*)d_in[8];
    const float* mf    = (const float*)d_in[9];
    const float* hf    = (const float*)d_in[10];
    float* out = (float*)d_out;

    k_fft<<<1024, 256>>>(x, lf, mf, hf);
    k_gemm1<<<dim3(8, 24), 256, GSMEM_BYTES>>>(W1, b1);
    k_gemm2<<<dim3(8, 16), 256, GSMEM_BYTES>>>(W2, b2);
    k_stats<<<1, 1024>>>();
    k_final<<<1024, 256>>>(wproj, gamma, beta, out);
}